// round 14
// baseline (speedup 1.0000x reference)
#include <cuda_runtime.h>
#include <cuda_bf16.h>
#include <math.h>

#define B_ 64
#define F_ 256
#define T_ 1024
#define H_ 1024
#define O_ 512

#define NB   128          // persistent blocks: 4 (bm) x 32 (ht)
#define KCH  256          // k chunk for s staging
#define NCHK 4            // chunks per step

// k_rnn smem layout (bf16 units)
#define WH_STRIDE 40                       // 32 cols + 8 pad
#define A_STRIDE  264                      // 256 k + 8 pad
#define OFF_WHH 0
#define OFF_WHL (1024 * WH_STRIDE)         // 40960
#define OFF_AH  (2 * 1024 * WH_STRIDE)     // 81920
#define A_BUF   (16 * A_STRIDE)            // 4224
#define OFF_AL  (OFF_AH + 2 * A_BUF)       // 90368
#define SMEM_RNN ((OFF_AL + 2 * A_BUF) * 2)  // 197,632 bytes

// xb buffer (written by k_xw, read-only for k_rnn): buf[t][b][h]
__device__ float g_buf[(size_t)T_ * B_ * H_];          // 256 MB
// bf16 hi/lo state copies: [t*B+b][h]
__device__ __nv_bfloat16 g_sh[(size_t)T_ * B_ * H_];   // 128 MB
__device__ __nv_bfloat16 g_sl[(size_t)T_ * B_ * H_];   // 128 MB
// bf16 split Wout
__device__ __nv_bfloat16 g_wh[H_ * O_];
__device__ __nv_bfloat16 g_wl[H_ * O_];
// per-block monotonic step flags (dataflow sync; replaces the global barrier)
__device__ unsigned g_flags[NB];

// ---------------------------------------------------------------------------
// Wait until the 8 producer blocks' flags (one 32B line) reach target.
// Volatile v4 loads bypass L1 (no stale-line deadlock); same addresses for
// all lanes -> broadcast, 1 request/warp/poll.
// ---------------------------------------------------------------------------
__device__ __forceinline__ void wait8(const unsigned* f, unsigned target) {
    for (;;) {
        unsigned a0, a1, a2, a3, b0, b1, b2, b3;
        asm volatile("ld.volatile.global.v4.u32 {%0,%1,%2,%3}, [%4];"
                     : "=r"(a0), "=r"(a1), "=r"(a2), "=r"(a3) : "l"(f));
        asm volatile("ld.volatile.global.v4.u32 {%0,%1,%2,%3}, [%4];"
                     : "=r"(b0), "=r"(b1), "=r"(b2), "=r"(b3) : "l"(f + 4));
        int d = (int)(a0 - target);
        d = min(d, (int)(a1 - target)); d = min(d, (int)(a2 - target));
        d = min(d, (int)(a3 - target)); d = min(d, (int)(b0 - target));
        d = min(d, (int)(b1 - target)); d = min(d, (int)(b2 - target));
        d = min(d, (int)(b3 - target));
        if (d >= 0) return;
        __nanosleep(30);
    }
}

// ---- mma helpers (proven) ----
__device__ __forceinline__ unsigned smem_u32(const void* p) {
    return (unsigned)__cvta_generic_to_shared(p);
}
__device__ __forceinline__ void ldsm4(unsigned* r, unsigned a) {
    asm volatile("ldmatrix.sync.aligned.m8n8.x4.shared.b16 {%0,%1,%2,%3}, [%4];"
        : "=r"(r[0]), "=r"(r[1]), "=r"(r[2]), "=r"(r[3]) : "r"(a));
}
__device__ __forceinline__ void ldsm4t(unsigned* r, unsigned a) {
    asm volatile("ldmatrix.sync.aligned.m8n8.x4.trans.shared.b16 {%0,%1,%2,%3}, [%4];"
        : "=r"(r[0]), "=r"(r[1]), "=r"(r[2]), "=r"(r[3]) : "r"(a));
}
__device__ __forceinline__ void mma16816(float* c, const unsigned* a,
                                         const unsigned* b) {
    asm volatile(
        "mma.sync.aligned.m16n8k16.row.col.f32.bf16.bf16.f32 "
        "{%0,%1,%2,%3}, {%4,%5,%6,%7}, {%8,%9}, {%0,%1,%2,%3};"
        : "+f"(c[0]), "+f"(c[1]), "+f"(c[2]), "+f"(c[3])
        : "r"(a[0]), "r"(a[1]), "r"(a[2]), "r"(a[3]), "r"(b[0]), "r"(b[1]));
}

// ---------------------------------------------------------------------------
// Kernel 0: one-shot Wout -> bf16 hi/lo split
// ---------------------------------------------------------------------------
__global__ void k_cvtW(const float* __restrict__ Wout) {
    int i = blockIdx.x * 256 + threadIdx.x;
    if (i < H_ * O_) {
        float v = Wout[i];
        __nv_bfloat16 h = __float2bfloat16(v);
        g_wh[i] = h;
        g_wl[i] = __float2bfloat16(v - __bfloat162float(h));
    }
}

// ---------------------------------------------------------------------------
// Kernel 1: buf[t][b][h] = bias[h] + sum_f x[b][f][t] * Wx[f][h]  (unchanged)
// ---------------------------------------------------------------------------
__global__ __launch_bounds__(256) void k_xw(const float* __restrict__ x,
                                            const float* __restrict__ Wx,
                                            const float* __restrict__ bias) {
    const int BM = 128, BN = 128, BK = 8, NC = F_ / BK;
    __shared__ float As[2][BK][BM];
    __shared__ float Bs[2][BK][BN];

    int tid = threadIdx.x;
    int tx = tid % 16, ty = tid / 16;
    int n0 = blockIdx.x * BN;
    int mtile = blockIdx.y;
    int b  = mtile / (T_ / BM);
    int t0 = (mtile % (T_ / BM)) * BM;

    const float* xb = x + (size_t)b * F_ * T_ + t0;

    const int lk = tid >> 5;
    const int lq = (tid & 31) * 4;

    float4 ra = *reinterpret_cast<const float4*>(&xb[(size_t)lk * T_ + lq]);
    float4 rb = *reinterpret_cast<const float4*>(&Wx[(size_t)lk * H_ + n0 + lq]);
    *reinterpret_cast<float4*>(&As[0][lk][lq]) = ra;
    *reinterpret_cast<float4*>(&Bs[0][lk][lq]) = rb;
    __syncthreads();

    float acc[8][8];
#pragma unroll
    for (int i = 0; i < 8; i++)
#pragma unroll
        for (int j = 0; j < 8; j++) acc[i][j] = 0.f;

    for (int c = 0; c < NC; ++c) {
        int cur = c & 1;
        if (c + 1 < NC) {
            ra = *reinterpret_cast<const float4*>(
                &xb[(size_t)((c + 1) * BK + lk) * T_ + lq]);
            rb = *reinterpret_cast<const float4*>(
                &Wx[(size_t)((c + 1) * BK + lk) * H_ + n0 + lq]);
        }
#pragma unroll
        for (int k = 0; k < BK; k++) {
            float va[8], vb[8];
#pragma unroll
            for (int i = 0; i < 8; i++) va[i] = As[cur][k][ty + 16 * i];
#pragma unroll
            for (int j = 0; j < 8; j++) vb[j] = Bs[cur][k][tx + 16 * j];
#pragma unroll
            for (int i = 0; i < 8; i++)
#pragma unroll
                for (int j = 0; j < 8; j++) acc[i][j] += va[i] * vb[j];
        }
        if (c + 1 < NC) {
            *reinterpret_cast<float4*>(&As[1 - cur][lk][lq]) = ra;
            *reinterpret_cast<float4*>(&Bs[1 - cur][lk][lq]) = rb;
            __syncthreads();
        }
    }

#pragma unroll
    for (int i = 0; i < 8; i++) {
        int t = t0 + ty + 16 * i;
        float* dst = g_buf + ((size_t)t * B_ + b) * H_ + n0;
#pragma unroll
        for (int j = 0; j < 8; j++) {
            int n = tx + 16 * j;
            dst[n] = acc[i][j] + bias[n0 + n];
        }
    }
}

// ---------------------------------------------------------------------------
// Kernel 2: persistent recurrence on tensor cores, DATAFLOW-synchronized.
// Block bx = (bm, ht): C[16 b][32 h], full K=1024.
// Chunk c of s_{t-1} (k in [c*256,(c+1)*256)) is produced by the 8 blocks
// (bm, c*8..c*8+7): wait on exactly those flags before loading it.
// After writing its own step-t tile, a block publishes its flag and moves on.
// No global barrier anywhere.
// ---------------------------------------------------------------------------
__global__ __launch_bounds__(128, 1) void k_rnn(const float* __restrict__ Wh) {
    extern __shared__ __nv_bfloat16 sm[];
    __nv_bfloat16* whh = sm + OFF_WHH;    // [1024][WH_STRIDE]
    __nv_bfloat16* whl = sm + OFF_WHL;

    const int tid  = threadIdx.x;
    const int lane = tid & 31;
    const int warp = tid >> 5;
    const int bx = blockIdx.x;
    const int bm = bx >> 5;               // 0..3  (16 b rows)
    const int ht = bx & 31;               // 0..31 (32 h cols)
    const int b0 = bm * 16;
    const int n0 = ht * 32;
    const int grp = bm * 32;              // first flag index of my group

    // one-time: convert Wh[:, n0:n0+32] -> bf16 hi/lo in smem
    for (int idx = tid; idx < 1024 * 8; idx += 128) {
        int row = idx >> 3, q = (idx & 7) * 4;
        float4 v = *reinterpret_cast<const float4*>(
            &Wh[(size_t)row * H_ + n0 + q]);
        __nv_bfloat16* dh = &whh[row * WH_STRIDE + q];
        __nv_bfloat16* dl = &whl[row * WH_STRIDE + q];
        __nv_bfloat16 h;
        h = __float2bfloat16(v.x); dh[0] = h; dl[0] = __float2bfloat16(v.x - __bfloat162float(h));
        h = __float2bfloat16(v.y); dh[1] = h; dl[1] = __float2bfloat16(v.y - __bfloat162float(h));
        h = __float2bfloat16(v.z); dh[2] = h; dl[2] = __float2bfloat16(v.z - __bfloat162float(h));
        h = __float2bfloat16(v.w); dh[3] = h; dl[3] = __float2bfloat16(v.w - __bfloat162float(h));
    }
    __syncthreads();

    // replay-safe base: all flags are equal at launch (previous run completed)
    unsigned base;
    asm volatile("ld.volatile.global.u32 %0, [%1];"
                 : "=r"(base) : "l"(&g_flags[bx]));

    // mma fragment geometry
    const int lrow = lane & 15;
    const int lcol = (lane >> 4) << 3;
    const int r0 = lane >> 2;
    const int c0 = (lane & 3) * 2;
    const int hb = n0 + (warp >> 1) * 16 + (warp & 1) * 8;
    const int gb0 = b0 + r0, gb1 = b0 + r0 + 8;
    const int gh  = hb + c0;
    const int bcol = (warp >> 1) * 16 + lcol;

    // prefetch xb for t = 0
    float2 xbA = *reinterpret_cast<const float2*>(&g_buf[(size_t)gb0 * H_ + gh]);
    float2 xbB = *reinterpret_cast<const float2*>(&g_buf[(size_t)gb1 * H_ + gh]);

    for (int t = 0; t < T_; ++t) {
        float acc[4] = {0.f, 0.f, 0.f, 0.f};

        if (t > 0) {
            const unsigned target = base + (unsigned)t;
            const __nv_bfloat16* sph = g_sh + ((size_t)(t - 1) * B_ + b0) * H_;
            const __nv_bfloat16* spl = g_sl + ((size_t)(t - 1) * B_ + b0) * H_;

            // wait for chunk-0 producers, then preload chunk 0
            wait8(&g_flags[grp], target);
            uint4 pvh[2], pvl[2];
#pragma unroll
            for (int it = 0; it < 2; it++) {
                int idx = it * 128 + tid;
                int row = idx >> 4, k16 = idx & 15;
                size_t src = (size_t)row * H_ + k16 * 16;
                pvh[it] = *reinterpret_cast<const uint4*>(&sph[src]);
                pvl[it] = *reinterpret_cast<const uint4*>(&spl[src]);
            }

            for (int c = 0; c < NCHK; ++c) {
                __nv_bfloat16* ah_s = sm + OFF_AH + (c & 1) * A_BUF;
                __nv_bfloat16* al_s = sm + OFF_AL + (c & 1) * A_BUF;
                __syncthreads();
#pragma unroll
                for (int it = 0; it < 2; it++) {
                    int idx = it * 128 + tid;
                    int row = idx >> 4, k16 = idx & 15;
                    size_t src = (size_t)row * H_ + c * KCH + k16 * 16;
                    uint4 h2 = *reinterpret_cast<const uint4*>(&sph[src + 8]);
                    uint4 l2 = *reinterpret_cast<const uint4*>(&spl[src + 8]);
                    __nv_bfloat16* da = &ah_s[row * A_STRIDE + k16 * 16];
                    __nv_bfloat16* dl = &al_s[row * A_STRIDE + k16 * 16];
                    *reinterpret_cast<uint4*>(da)     = pvh[it];
                    *reinterpret_cast<uint4*>(da + 8) = h2;
                    *reinterpret_cast<uint4*>(dl)     = pvl[it];
                    *reinterpret_cast<uint4*>(dl + 8) = l2;
                }
                __syncthreads();
                if (c + 1 < NCHK) {
                    // wait for chunk c+1 producers, then prefetch it
                    wait8(&g_flags[grp + (c + 1) * 8], target);
#pragma unroll
                    for (int it = 0; it < 2; it++) {
                        int idx = it * 128 + tid;
                        int row = idx >> 4, k16 = idx & 15;
                        size_t src = (size_t)row * H_ + (c + 1) * KCH + k16 * 16;
                        pvh[it] = *reinterpret_cast<const uint4*>(&sph[src]);
                        pvl[it] = *reinterpret_cast<const uint4*>(&spl[src]);
                    }
                }
                // compute chunk: 16 k16-steps
#pragma unroll 4
                for (int ks = 0; ks < KCH / 16; ks++) {
                    unsigned ah[4], al[4], bh[4], bl[4];
                    unsigned aA = smem_u32(&ah_s[lrow * A_STRIDE + ks * 16 + lcol]);
                    ldsm4(ah, aA);
                    unsigned aL = smem_u32(&al_s[lrow * A_STRIDE + ks * 16 + lcol]);
                    ldsm4(al, aL);
                    int kg = c * KCH + ks * 16;
                    unsigned bA = smem_u32(&whh[(kg + lrow) * WH_STRIDE + bcol]);
                    ldsm4t(bh, bA);
                    unsigned bL = smem_u32(&whl[(kg + lrow) * WH_STRIDE + bcol]);
                    ldsm4t(bl, bL);
                    const unsigned* bhp = &bh[(warp & 1) * 2];
                    const unsigned* blp = &bl[(warp & 1) * 2];
                    mma16816(acc, ah, bhp);
                    mma16816(acc, ah, blp);
                    mma16816(acc, al, bhp);
                }
            }
        }

        // epilogue: s_t = tanh(xb + acc); write bf16 hi/lo
        {
            float s0x = tanhf(xbA.x + acc[0]);
            float s0y = tanhf(xbA.y + acc[1]);
            float s1x = tanhf(xbB.x + acc[2]);
            float s1y = tanhf(xbB.y + acc[3]);
            size_t m0i = ((size_t)t * B_ + gb0) * H_ + gh;
            size_t m1i = ((size_t)t * B_ + gb1) * H_ + gh;
            __nv_bfloat16 h0x = __float2bfloat16(s0x);
            __nv_bfloat16 h0y = __float2bfloat16(s0y);
            __nv_bfloat16 h1x = __float2bfloat16(s1x);
            __nv_bfloat16 h1y = __float2bfloat16(s1y);
            __nv_bfloat162 p;
            p.x = h0x; p.y = h0y;
            *reinterpret_cast<__nv_bfloat162*>(&g_sh[m0i]) = p;
            p.x = h1x; p.y = h1y;
            *reinterpret_cast<__nv_bfloat162*>(&g_sh[m1i]) = p;
            p.x = __float2bfloat16(s0x - __bfloat162float(h0x));
            p.y = __float2bfloat16(s0y - __bfloat162float(h0y));
            *reinterpret_cast<__nv_bfloat162*>(&g_sl[m0i]) = p;
            p.x = __float2bfloat16(s1x - __bfloat162float(h1x));
            p.y = __float2bfloat16(s1y - __bfloat162float(h1y));
            *reinterpret_cast<__nv_bfloat162*>(&g_sl[m1i]) = p;
        }

        // publish: my step-t tile is globally visible
        __syncthreads();
        if (tid == 0) {
            __threadfence();
            *(volatile unsigned*)&g_flags[bx] = base + (unsigned)(t + 1);
        }

        // prefetch next step's xb (overlaps consumers' progress)
        {
            const float* nxt = g_buf + (size_t)((t + 1 < T_) ? t + 1 : t) * B_ * H_;
            xbA = *reinterpret_cast<const float2*>(&nxt[(size_t)gb0 * H_ + gh]);
            xbB = *reinterpret_cast<const float2*>(&nxt[(size_t)gb1 * H_ + gh]);
        }
    }
}

// ---------------------------------------------------------------------------
// Kernel 3: out = states @ Wout + bout via split-bf16 mma (proven, 576us).
// ---------------------------------------------------------------------------
#define AST 40
#define BST 136

__global__ __launch_bounds__(256, 2) void k_out_mma(const float* __restrict__ bout,
                                                    float* __restrict__ out) {
    __shared__ __nv_bfloat16 Ah[128 * AST];
    __shared__ __nv_bfloat16 Al[128 * AST];
    __shared__ __nv_bfloat16 Bh[32 * BST];
    __shared__ __nv_bfloat16 Bl[32 * BST];

    const int tid  = threadIdx.x;
    const int lane = tid & 31;
    const int warp = tid >> 5;
    const int wy = warp & 3;
    const int wx = warp >> 2;
    const int mw = wy * 32;
    const int nw = wx * 64;
    const int n0 = blockIdx.x * 128;
    const int m0 = blockIdx.y * 128;

    const int lrow = lane & 15;
    const int lcol = (lane >> 4) << 3;

    float acc[2][8][4];
#pragma unroll
    for (int i = 0; i < 2; i++)
#pragma unroll
        for (int j = 0; j < 8; j++)
#pragma unroll
            for (int r = 0; r < 4; r++) acc[i][j][r] = 0.f;

    const int achunk = tid & 3,  arow = tid >> 2;
    const int bchunk = tid & 15, brow = tid >> 4;

    for (int kc = 0; kc < H_; kc += 32) {
        __syncthreads();
#pragma unroll
        for (int p = 0; p < 2; p++) {
            int row = arow + p * 64;
            size_t src = (size_t)(m0 + row) * H_ + kc + achunk * 8;
            *reinterpret_cast<uint4*>(&Ah[row * AST + achunk * 8]) =
                *reinterpret_cast<const uint4*>(&g_sh[src]);
            *reinterpret_cast<uint4*>(&Al[row * AST + achunk * 8]) =
                *reinterpret_cast<const uint4*>(&g_sl[src]);
        }
#pragma unroll
        for (int p = 0; p < 2; p++) {
            int row = brow + p * 16;
            size_t src = (size_t)(kc + row) * O_ + n0 + bchunk * 8;
            *reinterpret_cast<uint4*>(&Bh[row * BST + bchunk * 8]) =
                *reinterpret_cast<const uint4*>(&g_wh[src]);
            *reinterpret_cast<uint4*>(&Bl[row * BST + bchunk * 8]) =
                *reinterpret_cast<const uint4*>(&g_wl[src]);
        }
        __syncthreads();

#pragma unroll
        for (int kk = 0; kk < 2; kk++) {
            const int ks = kk * 16;
            unsigned ah[2][4], al[2][4];
#pragma unroll
            for (int fm = 0; fm < 2; fm++) {
                unsigned a1 = smem_u32(&Ah[(mw + fm * 16 + lrow) * AST + ks + lcol]);
                ldsm4(ah[fm], a1);
                unsigned a2 = smem_u32(&Al[(mw + fm * 16 + lrow) * AST + ks + lcol]);
                ldsm4(al[fm], a2);
            }
#pragma unroll
            for (int np = 0; np < 4; np++) {
                unsigned bh[4], bl[4];
                unsigned ba = smem_u32(&Bh[(ks + lrow) * BST + nw + np * 16 + lcol]);
                ldsm4t(bh, ba);
                unsigned bb = smem_u32(&Bl[(ks + lrow) * BST + nw + np * 16 + lcol]);
                ldsm4t(bl, bb);
#pragma unroll
                for (int half = 0; half < 2; half++) {
                    const int fn = np * 2 + half;
                    const unsigned* bhp = &bh[half * 2];
                    const unsigned* blp = &bl[half * 2];
                    mma16816(acc[0][fn], ah[0], bhp);
                    mma16816(acc[1][fn], ah[1], bhp);
                    mma16816(acc[0][fn], ah[0], blp);
                    mma16816(acc[1][fn], ah[1], blp);
                    mma16816(acc[0][fn], al[0], bhp);
                    mma16816(acc[1][fn], al[1], bhp);
                }
            }
        }
    }

    const int g  = lane >> 2;
    const int c2 = (lane & 3) * 2;
#pragma unroll
    for (int fm = 0; fm < 2; fm++) {
#pragma unroll
        for (int fn = 0; fn < 8; fn++) {
            int n = n0 + nw + fn * 8 + c2;
            float b0v = bout[n], b1v = bout[n + 1];
#pragma unroll
            for (int half = 0; half < 2; half++) {
                int m = m0 + mw + fm * 16 + g + half * 8;
                int t = m >> 6;
                int b = m & 63;
                float* dst = out + ((size_t)b * T_ + t) * O_ + n;
                dst[0] = acc[fm][fn][half * 2 + 0] + b0v;
                dst[1] = acc[fm][fn][half * 2 + 1] + b1v;
            }
        }
    }
}

extern "C" void kernel_launch(void* const* d_in, const int* in_sizes, int n_in,
                              void* d_out, int out_size) {
    const float* x    = (const float*)d_in[0];
    const float* Wx   = (const float*)d_in[1];
    const float* Wh   = (const float*)d_in[2];
    const float* bias = (const float*)d_in[3];
    const float* Wout = (const float*)d_in[4];
    const float* bout = (const float*)d_in[5];
    float* out = (float*)d_out;

    (void)in_sizes; (void)n_in; (void)out_size;

    cudaFuncSetAttribute(k_rnn, cudaFuncAttributeMaxDynamicSharedMemorySize,
                         SMEM_RNN);

    k_cvtW<<<(H_ * O_ + 255) / 256, 256>>>(Wout);

    dim3 g1(H_ / 128, (B_ * T_) / 128);   // (8, 512)
    k_xw<<<g1, 256>>>(x, Wx, bias);

    k_rnn<<<NB, 128, SMEM_RNN>>>(Wh);     // single persistent launch

    dim3 g3(O_ / 128, (B_ * T_) / 128);   // (4, 512)
    k_out_mma<<<g3, 256>>>(bout, out);
}

// round 15
// speedup vs baseline: 1.4170x; 1.4170x over previous
#include <cuda_runtime.h>
#include <cuda_bf16.h>
#include <math.h>

#define B_ 64
#define F_ 256
#define T_ 1024
#define H_ 1024
#define O_ 512

#define NB   128          // persistent blocks: 4 (bm) x 32 (ht)
#define KCH  256          // k chunk for s staging
#define NCHK 4            // chunks per step

// k_rnn smem layout (bf16 units)
#define WH_STRIDE 40                       // 32 cols + 8 pad
#define A_STRIDE  264                      // 256 k + 8 pad
#define OFF_WHH 0
#define OFF_WHL (1024 * WH_STRIDE)         // 40960
#define OFF_AH  (2 * 1024 * WH_STRIDE)     // 81920
#define A_BUF   (16 * A_STRIDE)            // 4224
#define OFF_AL  (OFF_AH + 2 * A_BUF)       // 90368
#define SMEM_RNN ((OFF_AL + 2 * A_BUF) * 2)  // 197,632 bytes

// xb buffer (written by k_xw, read-only for k_rnn): buf[t][b][h]
__device__ float g_buf[(size_t)T_ * B_ * H_];          // 256 MB
// bf16 hi/lo state copies: [t*B+b][h]
__device__ __nv_bfloat16 g_sh[(size_t)T_ * B_ * H_];   // 128 MB
__device__ __nv_bfloat16 g_sl[(size_t)T_ * B_ * H_];   // 128 MB
// bf16 split Wout
__device__ __nv_bfloat16 g_wh[H_ * O_];
__device__ __nv_bfloat16 g_wl[H_ * O_];
__device__ unsigned g_flags[NB];
__device__ unsigned g_rel2;

// ---------------------------------------------------------------------------
// PROVEN R3/R7/R12 barrier: distributed arrival flags, leader scans, one
// release word. Monotonic epochs -> graph-replay safe.
// ---------------------------------------------------------------------------
__device__ __forceinline__ void gsync(unsigned target) {
    __syncthreads();
    if (blockIdx.x == 0) {
        if (threadIdx.x == 0) {
            __threadfence();
            *(volatile unsigned*)&g_flags[0] = target;
        }
        unsigned i = threadIdx.x;
        while ((int)(*(volatile unsigned*)&g_flags[i] - target) < 0)
            __nanosleep(40);
        __syncthreads();
        if (threadIdx.x == 0) {
            __threadfence();
            *(volatile unsigned*)&g_rel2 = target;
        }
        __syncthreads();
    } else {
        if (threadIdx.x == 0) {
            __threadfence();
            *(volatile unsigned*)&g_flags[blockIdx.x] = target;
            while ((int)(*(volatile unsigned*)&g_rel2 - target) < 0)
                __nanosleep(40);
            __threadfence();
        }
        __syncthreads();
    }
}

// ---- mma helpers (proven) ----
__device__ __forceinline__ unsigned smem_u32(const void* p) {
    return (unsigned)__cvta_generic_to_shared(p);
}
__device__ __forceinline__ void ldsm4(unsigned* r, unsigned a) {
    asm volatile("ldmatrix.sync.aligned.m8n8.x4.shared.b16 {%0,%1,%2,%3}, [%4];"
        : "=r"(r[0]), "=r"(r[1]), "=r"(r[2]), "=r"(r[3]) : "r"(a));
}
__device__ __forceinline__ void ldsm2t(unsigned* r, unsigned a) {
    asm volatile("ldmatrix.sync.aligned.m8n8.x2.trans.shared.b16 {%0,%1}, [%2];"
        : "=r"(r[0]), "=r"(r[1]) : "r"(a));
}
__device__ __forceinline__ void ldsm4t(unsigned* r, unsigned a) {
    asm volatile("ldmatrix.sync.aligned.m8n8.x4.trans.shared.b16 {%0,%1,%2,%3}, [%4];"
        : "=r"(r[0]), "=r"(r[1]), "=r"(r[2]), "=r"(r[3]) : "r"(a));
}
__device__ __forceinline__ void mma16816(float* c, const unsigned* a,
                                         const unsigned* b) {
    asm volatile(
        "mma.sync.aligned.m16n8k16.row.col.f32.bf16.bf16.f32 "
        "{%0,%1,%2,%3}, {%4,%5,%6,%7}, {%8,%9}, {%0,%1,%2,%3};"
        : "+f"(c[0]), "+f"(c[1]), "+f"(c[2]), "+f"(c[3])
        : "r"(a[0]), "r"(a[1]), "r"(a[2]), "r"(a[3]), "r"(b[0]), "r"(b[1]));
}

// ---------------------------------------------------------------------------
// Kernel 0: one-shot Wout -> bf16 hi/lo split
// ---------------------------------------------------------------------------
__global__ void k_cvtW(const float* __restrict__ Wout) {
    int i = blockIdx.x * 256 + threadIdx.x;
    if (i < H_ * O_) {
        float v = Wout[i];
        __nv_bfloat16 h = __float2bfloat16(v);
        g_wh[i] = h;
        g_wl[i] = __float2bfloat16(v - __bfloat162float(h));
    }
}

// ---------------------------------------------------------------------------
// Kernel 1: buf[t][b][h] = bias[h] + sum_f x[b][f][t] * Wx[f][h]  (unchanged)
// ---------------------------------------------------------------------------
__global__ __launch_bounds__(256) void k_xw(const float* __restrict__ x,
                                            const float* __restrict__ Wx,
                                            const float* __restrict__ bias) {
    const int BM = 128, BN = 128, BK = 8, NC = F_ / BK;
    __shared__ float As[2][BK][BM];
    __shared__ float Bs[2][BK][BN];

    int tid = threadIdx.x;
    int tx = tid % 16, ty = tid / 16;
    int n0 = blockIdx.x * BN;
    int mtile = blockIdx.y;
    int b  = mtile / (T_ / BM);
    int t0 = (mtile % (T_ / BM)) * BM;

    const float* xb = x + (size_t)b * F_ * T_ + t0;

    const int lk = tid >> 5;
    const int lq = (tid & 31) * 4;

    float4 ra = *reinterpret_cast<const float4*>(&xb[(size_t)lk * T_ + lq]);
    float4 rb = *reinterpret_cast<const float4*>(&Wx[(size_t)lk * H_ + n0 + lq]);
    *reinterpret_cast<float4*>(&As[0][lk][lq]) = ra;
    *reinterpret_cast<float4*>(&Bs[0][lk][lq]) = rb;
    __syncthreads();

    float acc[8][8];
#pragma unroll
    for (int i = 0; i < 8; i++)
#pragma unroll
        for (int j = 0; j < 8; j++) acc[i][j] = 0.f;

    for (int c = 0; c < NC; ++c) {
        int cur = c & 1;
        if (c + 1 < NC) {
            ra = *reinterpret_cast<const float4*>(
                &xb[(size_t)((c + 1) * BK + lk) * T_ + lq]);
            rb = *reinterpret_cast<const float4*>(
                &Wx[(size_t)((c + 1) * BK + lk) * H_ + n0 + lq]);
        }
#pragma unroll
        for (int k = 0; k < BK; k++) {
            float va[8], vb[8];
#pragma unroll
            for (int i = 0; i < 8; i++) va[i] = As[cur][k][ty + 16 * i];
#pragma unroll
            for (int j = 0; j < 8; j++) vb[j] = Bs[cur][k][tx + 16 * j];
#pragma unroll
            for (int i = 0; i < 8; i++)
#pragma unroll
                for (int j = 0; j < 8; j++) acc[i][j] += va[i] * vb[j];
        }
        if (c + 1 < NC) {
            *reinterpret_cast<float4*>(&As[1 - cur][lk][lq]) = ra;
            *reinterpret_cast<float4*>(&Bs[1 - cur][lk][lq]) = rb;
            __syncthreads();
        }
    }

#pragma unroll
    for (int i = 0; i < 8; i++) {
        int t = t0 + ty + 16 * i;
        float* dst = g_buf + ((size_t)t * B_ + b) * H_ + n0;
#pragma unroll
        for (int j = 0; j < 8; j++) {
            int n = tx + 16 * j;
            dst[n] = acc[i][j] + bias[n0 + n];
        }
    }
}

// ---------------------------------------------------------------------------
// Kernel 2: persistent recurrence on tensor cores (R12 skeleton).
// Changes vs R12:
//   - 3 independent accumulator chains (Ah@Bh / Ah@Bl / Al@Bh), summed in
//     the epilogue -> mma dependency chain 192 -> 64.
//   - B fragments via ldmatrix.x2.trans at the warp's exact n8 slice
//     (R12 loaded x4 and discarded half).
// ---------------------------------------------------------------------------
__global__ __launch_bounds__(128, 1) void k_rnn(const float* __restrict__ Wh) {
    extern __shared__ __nv_bfloat16 sm[];
    __nv_bfloat16* whh = sm + OFF_WHH;    // [1024][WH_STRIDE]
    __nv_bfloat16* whl = sm + OFF_WHL;

    const int tid  = threadIdx.x;
    const int lane = tid & 31;
    const int warp = tid >> 5;
    const int bx = blockIdx.x;
    const int bm = bx >> 5;               // 0..3  (16 b rows)
    const int ht = bx & 31;               // 0..31 (32 h cols)
    const int b0 = bm * 16;
    const int n0 = ht * 32;

    // one-time: convert Wh[:, n0:n0+32] -> bf16 hi/lo in smem
    for (int idx = tid; idx < 1024 * 8; idx += 128) {
        int row = idx >> 3, q = (idx & 7) * 4;
        float4 v = *reinterpret_cast<const float4*>(
            &Wh[(size_t)row * H_ + n0 + q]);
        __nv_bfloat16* dh = &whh[row * WH_STRIDE + q];
        __nv_bfloat16* dl = &whl[row * WH_STRIDE + q];
        __nv_bfloat16 h;
        h = __float2bfloat16(v.x); dh[0] = h; dl[0] = __float2bfloat16(v.x - __bfloat162float(h));
        h = __float2bfloat16(v.y); dh[1] = h; dl[1] = __float2bfloat16(v.y - __bfloat162float(h));
        h = __float2bfloat16(v.z); dh[2] = h; dl[2] = __float2bfloat16(v.z - __bfloat162float(h));
        h = __float2bfloat16(v.w); dh[3] = h; dl[3] = __float2bfloat16(v.w - __bfloat162float(h));
    }
    __syncthreads();

    unsigned base = *(volatile unsigned*)&g_rel2;
    unsigned bar = 0;

    // mma fragment geometry
    const int lrow = lane & 15;
    const int lcol = (lane >> 4) << 3;
    const int r0 = lane >> 2;
    const int c0 = (lane & 3) * 2;
    const int hb = n0 + (warp >> 1) * 16 + (warp & 1) * 8;  // warp's n8 base
    const int gb0 = b0 + r0, gb1 = b0 + r0 + 8;
    const int gh  = hb + c0;
    // B ldsm x2 column base: the warp's exact 8-column slice (local)
    const int bcol2 = (warp >> 1) * 16 + (warp & 1) * 8;

    // prefetch xb for t = 0
    float2 xbA = *reinterpret_cast<const float2*>(&g_buf[(size_t)gb0 * H_ + gh]);
    float2 xbB = *reinterpret_cast<const float2*>(&g_buf[(size_t)gb1 * H_ + gh]);

    for (int t = 0; t < T_; ++t) {
        float accA[4] = {0.f, 0.f, 0.f, 0.f};   // Ah @ Bh
        float accBv[4] = {0.f, 0.f, 0.f, 0.f};  // Ah @ Bl
        float accC[4] = {0.f, 0.f, 0.f, 0.f};   // Al @ Bh

        if (t > 0) {
            const __nv_bfloat16* sph = g_sh + ((size_t)(t - 1) * B_ + b0) * H_;
            const __nv_bfloat16* spl = g_sl + ((size_t)(t - 1) * B_ + b0) * H_;

            // preload chunk 0
            uint4 pvh[2], pvl[2];
#pragma unroll
            for (int it = 0; it < 2; it++) {
                int idx = it * 128 + tid;
                int row = idx >> 4, k16 = idx & 15;
                size_t src = (size_t)row * H_ + k16 * 16;
                pvh[it] = *reinterpret_cast<const uint4*>(&sph[src]);
                pvl[it] = *reinterpret_cast<const uint4*>(&spl[src]);
            }

            for (int c = 0; c < NCHK; ++c) {
                __nv_bfloat16* ah_s = sm + OFF_AH + (c & 1) * A_BUF;
                __nv_bfloat16* al_s = sm + OFF_AL + (c & 1) * A_BUF;
                __syncthreads();
#pragma unroll
                for (int it = 0; it < 2; it++) {
                    int idx = it * 128 + tid;
                    int row = idx >> 4, k16 = idx & 15;
                    size_t src = (size_t)row * H_ + c * KCH + k16 * 16;
                    uint4 h2 = *reinterpret_cast<const uint4*>(&sph[src + 8]);
                    uint4 l2 = *reinterpret_cast<const uint4*>(&spl[src + 8]);
                    __nv_bfloat16* da = &ah_s[row * A_STRIDE + k16 * 16];
                    __nv_bfloat16* dl = &al_s[row * A_STRIDE + k16 * 16];
                    *reinterpret_cast<uint4*>(da)     = pvh[it];
                    *reinterpret_cast<uint4*>(da + 8) = h2;
                    *reinterpret_cast<uint4*>(dl)     = pvl[it];
                    *reinterpret_cast<uint4*>(dl + 8) = l2;
                }
                __syncthreads();
                if (c + 1 < NCHK) {
#pragma unroll
                    for (int it = 0; it < 2; it++) {
                        int idx = it * 128 + tid;
                        int row = idx >> 4, k16 = idx & 15;
                        size_t src = (size_t)row * H_ + (c + 1) * KCH + k16 * 16;
                        pvh[it] = *reinterpret_cast<const uint4*>(&sph[src]);
                        pvl[it] = *reinterpret_cast<const uint4*>(&spl[src]);
                    }
                }
                // compute chunk: 16 k16-steps, 3 independent acc chains
#pragma unroll 4
                for (int ks = 0; ks < KCH / 16; ks++) {
                    unsigned ah[4], al[4], bh2[2], bl2[2];
                    unsigned aA = smem_u32(&ah_s[lrow * A_STRIDE + ks * 16 + lcol]);
                    ldsm4(ah, aA);
                    unsigned aL = smem_u32(&al_s[lrow * A_STRIDE + ks * 16 + lcol]);
                    ldsm4(al, aL);
                    int kg = c * KCH + ks * 16;
                    unsigned bA = smem_u32(&whh[(kg + lrow) * WH_STRIDE + bcol2]);
                    ldsm2t(bh2, bA);
                    unsigned bL = smem_u32(&whl[(kg + lrow) * WH_STRIDE + bcol2]);
                    ldsm2t(bl2, bL);
                    mma16816(accA, ah, bh2);
                    mma16816(accBv, ah, bl2);
                    mma16816(accC, al, bh2);
                }
            }
        }

        // epilogue: s_t = tanh(xb + accA+accB+accC); write bf16 hi/lo
        {
            float a0 = accA[0] + accBv[0] + accC[0];
            float a1 = accA[1] + accBv[1] + accC[1];
            float a2 = accA[2] + accBv[2] + accC[2];
            float a3 = accA[3] + accBv[3] + accC[3];
            float s0x = tanhf(xbA.x + a0);
            float s0y = tanhf(xbA.y + a1);
            float s1x = tanhf(xbB.x + a2);
            float s1y = tanhf(xbB.y + a3);
            size_t m0i = ((size_t)t * B_ + gb0) * H_ + gh;
            size_t m1i = ((size_t)t * B_ + gb1) * H_ + gh;
            __nv_bfloat16 h0x = __float2bfloat16(s0x);
            __nv_bfloat16 h0y = __float2bfloat16(s0y);
            __nv_bfloat16 h1x = __float2bfloat16(s1x);
            __nv_bfloat16 h1y = __float2bfloat16(s1y);
            __nv_bfloat162 p;
            p.x = h0x; p.y = h0y;
            *reinterpret_cast<__nv_bfloat162*>(&g_sh[m0i]) = p;
            p.x = h1x; p.y = h1y;
            *reinterpret_cast<__nv_bfloat162*>(&g_sh[m1i]) = p;
            p.x = __float2bfloat16(s0x - __bfloat162float(h0x));
            p.y = __float2bfloat16(s0y - __bfloat162float(h0y));
            *reinterpret_cast<__nv_bfloat162*>(&g_sl[m0i]) = p;
            p.x = __float2bfloat16(s1x - __bfloat162float(h1x));
            p.y = __float2bfloat16(s1y - __bfloat162float(h1y));
            *reinterpret_cast<__nv_bfloat162*>(&g_sl[m1i]) = p;
        }

        // prefetch next step's xb BEFORE the barrier
        {
            const float* nxt = g_buf + (size_t)((t + 1 < T_) ? t + 1 : t) * B_ * H_;
            xbA = *reinterpret_cast<const float2*>(&nxt[(size_t)gb0 * H_ + gh]);
            xbB = *reinterpret_cast<const float2*>(&nxt[(size_t)gb1 * H_ + gh]);
        }

        gsync(base + (++bar));
    }
}

// ---------------------------------------------------------------------------
// Kernel 3: out = states @ Wout + bout via split-bf16 mma (proven, 575us).
// ---------------------------------------------------------------------------
#define AST 40
#define BST 136

__global__ __launch_bounds__(256, 2) void k_out_mma(const float* __restrict__ bout,
                                                    float* __restrict__ out) {
    __shared__ __nv_bfloat16 Ah[128 * AST];
    __shared__ __nv_bfloat16 Al[128 * AST];
    __shared__ __nv_bfloat16 Bh[32 * BST];
    __shared__ __nv_bfloat16 Bl[32 * BST];

    const int tid  = threadIdx.x;
    const int lane = tid & 31;
    const int warp = tid >> 5;
    const int wy = warp & 3;
    const int wx = warp >> 2;
    const int mw = wy * 32;
    const int nw = wx * 64;
    const int n0 = blockIdx.x * 128;
    const int m0 = blockIdx.y * 128;

    const int lrow = lane & 15;
    const int lcol = (lane >> 4) << 3;

    float acc[2][8][4];
#pragma unroll
    for (int i = 0; i < 2; i++)
#pragma unroll
        for (int j = 0; j < 8; j++)
#pragma unroll
            for (int r = 0; r < 4; r++) acc[i][j][r] = 0.f;

    const int achunk = tid & 3,  arow = tid >> 2;
    const int bchunk = tid & 15, brow = tid >> 4;

    for (int kc = 0; kc < H_; kc += 32) {
        __syncthreads();
#pragma unroll
        for (int p = 0; p < 2; p++) {
            int row = arow + p * 64;
            size_t src = (size_t)(m0 + row) * H_ + kc + achunk * 8;
            *reinterpret_cast<uint4*>(&Ah[row * AST + achunk * 8]) =
                *reinterpret_cast<const uint4*>(&g_sh[src]);
            *reinterpret_cast<uint4*>(&Al[row * AST + achunk * 8]) =
                *reinterpret_cast<const uint4*>(&g_sl[src]);
        }
#pragma unroll
        for (int p = 0; p < 2; p++) {
            int row = brow + p * 16;
            size_t src = (size_t)(kc + row) * O_ + n0 + bchunk * 8;
            *reinterpret_cast<uint4*>(&Bh[row * BST + bchunk * 8]) =
                *reinterpret_cast<const uint4*>(&g_wh[src]);
            *reinterpret_cast<uint4*>(&Bl[row * BST + bchunk * 8]) =
                *reinterpret_cast<const uint4*>(&g_wl[src]);
        }
        __syncthreads();

#pragma unroll
        for (int kk = 0; kk < 2; kk++) {
            const int ks = kk * 16;
            unsigned ah[2][4], al[2][4];
#pragma unroll
            for (int fm = 0; fm < 2; fm++) {
                unsigned a1 = smem_u32(&Ah[(mw + fm * 16 + lrow) * AST + ks + lcol]);
                ldsm4(ah[fm], a1);
                unsigned a2 = smem_u32(&Al[(mw + fm * 16 + lrow) * AST + ks + lcol]);
                ldsm4(al[fm], a2);
            }
#pragma unroll
            for (int np = 0; np < 4; np++) {
                unsigned bh[4], bl[4];
                unsigned ba = smem_u32(&Bh[(ks + lrow) * BST + nw + np * 16 + lcol]);
                ldsm4t(bh, ba);
                unsigned bb = smem_u32(&Bl[(ks + lrow) * BST + nw + np * 16 + lcol]);
                ldsm4t(bl, bb);
#pragma unroll
                for (int half = 0; half < 2; half++) {
                    const int fn = np * 2 + half;
                    const unsigned* bhp = &bh[half * 2];
                    const unsigned* blp = &bl[half * 2];
                    mma16816(acc[0][fn], ah[0], bhp);
                    mma16816(acc[1][fn], ah[1], bhp);
                    mma16816(acc[0][fn], ah[0], blp);
                    mma16816(acc[1][fn], ah[1], blp);
                    mma16816(acc[0][fn], al[0], bhp);
                    mma16816(acc[1][fn], al[1], bhp);
                }
            }
        }
    }

    const int g  = lane >> 2;
    const int c2 = (lane & 3) * 2;
#pragma unroll
    for (int fm = 0; fm < 2; fm++) {
#pragma unroll
        for (int fn = 0; fn < 8; fn++) {
            int n = n0 + nw + fn * 8 + c2;
            float b0v = bout[n], b1v = bout[n + 1];
#pragma unroll
            for (int half = 0; half < 2; half++) {
                int m = m0 + mw + fm * 16 + g + half * 8;
                int t = m >> 6;
                int b = m & 63;
                float* dst = out + ((size_t)b * T_ + t) * O_ + n;
                dst[0] = acc[fm][fn][half * 2 + 0] + b0v;
                dst[1] = acc[fm][fn][half * 2 + 1] + b1v;
            }
        }
    }
}

extern "C" void kernel_launch(void* const* d_in, const int* in_sizes, int n_in,
                              void* d_out, int out_size) {
    const float* x    = (const float*)d_in[0];
    const float* Wx   = (const float*)d_in[1];
    const float* Wh   = (const float*)d_in[2];
    const float* bias = (const float*)d_in[3];
    const float* Wout = (const float*)d_in[4];
    const float* bout = (const float*)d_in[5];
    float* out = (float*)d_out;

    (void)in_sizes; (void)n_in; (void)out_size;

    cudaFuncSetAttribute(k_rnn, cudaFuncAttributeMaxDynamicSharedMemorySize,
                         SMEM_RNN);

    k_cvtW<<<(H_ * O_ + 255) / 256, 256>>>(Wout);

    dim3 g1(H_ / 128, (B_ * T_) / 128);   // (8, 512)
    k_xw<<<g1, 256>>>(x, Wx, bias);

    k_rnn<<<NB, 128, SMEM_RNN>>>(Wh);     // single persistent launch

    dim3 g3(O_ / 128, (B_ * T_) / 128);   // (4, 512)
    k_out_mma<<<g3, 256>>>(bout, out);
}